// round 1
// baseline (speedup 1.0000x reference)
#include <cuda_runtime.h>
#include <cuda_bf16.h>
#include <cstdint>

#define BATCH 4
#define HH 384
#define WW 384
#define NN 128
#define RAD 4
#define NSTEPS 50
#define CLIPMAX 382.999f

// ---------------- scratch (static device allocations) ----------------
__device__ float2 g_G [BATCH * HH * WW];   // grad image of pred,  {gy,gx} *10
__device__ float2 g_GW[BATCH * HH * WW];   // grad image of |pred|,{gy,gx} *10
__device__ float  g_M [NN * NN];
__device__ float  g_Mw[NN * NN];
__device__ float2 g_pts[BATCH * NN];
__device__ float  g_wid[BATCH * NN];
__device__ float  g_part[384];

// ---------------- helpers ----------------
__device__ __forceinline__ float fsqrt_approx(float x) {
    float r; asm("sqrt.approx.f32 %0, %1;" : "=f"(r) : "f"(x)); return r;
}

__device__ __forceinline__ float2 bilin(const float2* __restrict__ img, float y, float x) {
    y = fminf(fmaxf(y, 0.f), CLIPMAX);
    x = fminf(fmaxf(x, 0.f), CLIPMAX);
    float fy = floorf(y), fx = floorf(x);
    int   y0 = (int)fy,  x0 = (int)fx;
    float wy = y - fy,   wx = x - fx;
    const float2* p = img + y0 * WW + x0;
    float2 v00 = p[0], v01 = p[1], v10 = p[WW], v11 = p[WW + 1];
    float w00 = (1.f - wy) * (1.f - wx);
    float w01 = (1.f - wy) * wx;
    float w10 = wy * (1.f - wx);
    float w11 = wy * wx;
    float2 r;
    r.x = v00.x * w00 + v01.x * w01 + v10.x * w10 + v11.x * w11;
    r.y = v00.y * w00 + v01.y * w01 + v10.y * w10 + v11.y * w11;
    return r;
}

// ---------------- kernel 1: gradient images (9x9 conv, SAME, zero pad) ----------------
__global__ void conv_kernel(const float* __restrict__ pred) {
    __shared__ float2 tile[40][40];   // {p, |p|}
    const int bx = blockIdx.x * 32, by = blockIdx.y * 32, b = blockIdx.z;
    const float* img = pred + b * HH * WW;

    // Gaussian + derivative weights (match numpy float32 computation)
    float g[9], dg[9], s = 0.f;
#pragma unroll
    for (int k = 0; k < 9; k++) { float t = (float)(k - 4); g[k] = expf(-t * t * 0.125f); s += g[k]; }
    float inv = 1.f / s;
#pragma unroll
    for (int k = 0; k < 9; k++) { g[k] *= inv; dg[k] = -(float)(k - 4) * 0.25f * g[k]; }

    const int tx = threadIdx.x, ty = threadIdx.y;
    const int tid = ty * 32 + tx;
    for (int i = tid; i < 40 * 40; i += 256) {
        int ly = i / 40, lx = i % 40;
        int gy = by - RAD + ly, gx = bx - RAD + lx;
        float v = (gy >= 0 && gy < HH && gx >= 0 && gx < WW) ? img[gy * WW + gx] : 0.f;
        tile[ly][lx] = make_float2(v, fabsf(v));
    }
    __syncthreads();

#pragma unroll
    for (int s4 = 0; s4 < 4; s4++) {
        int oy = ty + s4 * 8;
        float a0 = 0.f, a1 = 0.f, b0 = 0.f, b1 = 0.f;
#pragma unroll
        for (int ky = 0; ky < 9; ky++) {
            float wdy = dg[ky], wgy = g[ky];
#pragma unroll
            for (int kx = 0; kx < 9; kx++) {
                float2 p = tile[oy + ky][tx + kx];
                float wfy = wdy * g[kx];    // channel 0 (y-grad)
                float wfx = wgy * dg[kx];   // channel 1 (x-grad)
                a0 = fmaf(wfy, p.x, a0); a1 = fmaf(wfx, p.x, a1);
                b0 = fmaf(wfy, p.y, b0); b1 = fmaf(wfx, p.y, b1);
            }
        }
        int gy = by + oy, gx = bx + tx;
        int o = (b * HH + gy) * WW + gx;
        g_G [o] = make_float2(10.f * a0, 10.f * a1);
        g_GW[o] = make_float2(10.f * b0, 10.f * b1);
    }
}

// ---------------- kernel 2: M, Mw via DCT eigenbasis of path Laplacian ----------------
// L = D^T D  (path graph Laplacian, free ends)
// eigvec q_k[i] ~ cos(pi*k*(2i+1)/(2n)),  eigval lam_k = 2 - 2 cos(pi*k/n)
// M  = sum_k c2_k /(1 + 0.001*lam + 0.001*lam^2) * q_k q_k^T
// Mw = sum_k c2_k /(1 + 0.001*lam)               * q_k q_k^T
__global__ void matgen_kernel() {
    const int i = blockIdx.x, j = threadIdx.x;
    __shared__ float am[NN], aw[NN];
    {
        int k = j;
        float lam = 2.f - 2.f * cospif((float)k / 128.f);
        float c2  = (k == 0 ? 1.f : 2.f) / 128.f;
        float dm  = 1.f / (1.f + 0.001f * lam + 0.001f * lam * lam);
        float dw  = 1.f / (1.f + 0.001f * lam);
        float a   = cospif((float)(k * (2 * i + 1)) / 256.f);
        am[k] = c2 * dm * a;
        aw[k] = c2 * dw * a;
    }
    __syncthreads();
    float sm = 0.f, sw = 0.f;
#pragma unroll 4
    for (int k = 0; k < NN; k++) {
        float bq = cospif((float)(k * (2 * j + 1)) / 256.f);
        sm = fmaf(am[k], bq, sm);
        sw = fmaf(aw[k], bq, sw);
    }
    g_M [i * NN + j] = sm;
    g_Mw[i * NN + j] = sw;
}

// ---------------- kernel 3: snake evolution (1 block / sample, 256 threads) ----------------
__global__ void __launch_bounds__(256) snake_kernel(const float* __restrict__ nodes) {
    const int b = blockIdx.x;
    const int tid = threadIdx.x;
    __shared__ __align__(16) float2 ps[NN];      // {y, x}
    __shared__ __align__(16) float  wd[NN];
    __shared__ __align__(16) float2 v2[NN];
    __shared__ __align__(16) float  vw[NN];
    __shared__ float2 part2[256];
    __shared__ float  partw[256];

    if (tid < NN) {
        ps[tid] = make_float2(nodes[(b * NN + tid) * 2], nodes[(b * NN + tid) * 2 + 1]);
        wd[tid] = 1.f;
    }
    __syncthreads();

    const float2* Gb  = g_G  + b * HH * WW;
    const float2* GWb = g_GW + b * HH * WW;

    const int row = tid & 127;
    const int jb  = (tid >> 7) * 64;
    // row-contiguous (matrices are symmetric so this equals the needed column)
    const float4* Mr  = reinterpret_cast<const float4*>(g_M  + row * NN + jb);
    const float4* Mwr = reinterpret_cast<const float4*>(g_Mw + row * NN + jb);

    for (int step = 0; step < NSTEPS; step++) {
        // phase 1: f = bilinear(G, pts); v = pts + 0.1 f
        if (tid < NN) {
            float2 p = ps[tid];
            float2 f = bilin(Gb, p.x, p.y);
            v2[tid] = make_float2(p.x + 0.1f * f.x, p.y + 0.1f * f.y);
        }
        __syncthreads();

        // phase 2: pts = M @ v   (j-split across thread halves)
        {
            float ay0 = 0.f, ax0 = 0.f, ay1 = 0.f, ax1 = 0.f;
            const float4* vv = reinterpret_cast<const float4*>(&v2[jb]);
#pragma unroll
            for (int q = 0; q < 16; q++) {
                float4 m  = __ldg(&Mr[q]);
                float4 va = vv[2 * q];        // v2[j], v2[j+1]
                float4 vb = vv[2 * q + 1];    // v2[j+2], v2[j+3]
                ay0 = fmaf(m.x, va.x, ay0); ax0 = fmaf(m.x, va.y, ax0);
                ay1 = fmaf(m.y, va.z, ay1); ax1 = fmaf(m.y, va.w, ax1);
                ay0 = fmaf(m.z, vb.x, ay0); ax0 = fmaf(m.z, vb.y, ax0);
                ay1 = fmaf(m.w, vb.z, ay1); ax1 = fmaf(m.w, vb.w, ax1);
            }
            part2[tid] = make_float2(ay0 + ay1, ax0 + ax1);
        }
        __syncthreads();

        // combine + phase 3: fw = ||bilinear(GW, new pts)||; vw = wid + 0.1 fw
        if (tid < NN) {
            float2 a = part2[tid], c = part2[tid + 128];
            float2 p = make_float2(a.x + c.x, a.y + c.y);
            ps[tid] = p;
            float2 fw = bilin(GWb, p.x, p.y);
            vw[tid] = wd[tid] + 0.1f * sqrtf(fw.x * fw.x + fw.y * fw.y);
        }
        __syncthreads();

        // phase 4: wid = Mw @ vw
        {
            float a0 = 0.f, a1 = 0.f;
            const float4* vv = reinterpret_cast<const float4*>(&vw[jb]);
#pragma unroll
            for (int q = 0; q < 16; q++) {
                float4 m = __ldg(&Mwr[q]);
                float4 v = vv[q];
                a0 = fmaf(m.x, v.x, a0); a1 = fmaf(m.y, v.y, a1);
                a0 = fmaf(m.z, v.z, a0); a1 = fmaf(m.w, v.w, a1);
            }
            partw[tid] = a0 + a1;
        }
        __syncthreads();
        if (tid < NN) wd[tid] = partw[tid] + partw[tid + 128];
        __syncthreads();
    }

    if (tid < NN) {
        g_pts[b * NN + tid] = ps[tid];
        g_wid[b * NN + tid] = wd[tid];
    }
}

// ---------------- kernel 4: render + squared-error partial sums ----------------
// grid (96, 4): x = row-group (4 rows), y = sample. block (96, 4): 4 px along x per thread.
__global__ void __launch_bounds__(384) render_kernel(const float* __restrict__ pred) {
    const int b  = blockIdx.y;
    const int y  = blockIdx.x * 4 + threadIdx.y;
    const int x0 = threadIdx.x * 4;
    const int tid = threadIdx.y * 96 + threadIdx.x;

    __shared__ float4 nsh[NN];   // {y, x, w, 0}
    if (tid < NN) {
        float2 p = g_pts[b * NN + tid];
        nsh[tid] = make_float4(p.x, p.y, g_wid[b * NN + tid], 0.f);
    }
    __syncthreads();

    const float fy  = (float)y;
    const float fx0 = (float)x0;
    float m0 = 3.4e38f, m1 = 3.4e38f, m2 = 3.4e38f, m3 = 3.4e38f;

#pragma unroll 4
    for (int k = 0; k < NN; k++) {
        float4 nd = nsh[k];
        float dy  = fy - nd.x;
        float dy2 = dy * dy;
        float dx0 = fx0 - nd.y;
        float dx1 = dx0 + 1.f, dx2 = dx0 + 2.f, dx3 = dx0 + 3.f;
        m0 = fminf(m0, fsqrt_approx(fmaf(dx0, dx0, dy2)) - nd.z);
        m1 = fminf(m1, fsqrt_approx(fmaf(dx1, dx1, dy2)) - nd.z);
        m2 = fminf(m2, fsqrt_approx(fmaf(dx2, dx2, dy2)) - nd.z);
        m3 = fminf(m3, fsqrt_approx(fmaf(dx3, dx3, dy2)) - nd.z);
    }
    m0 = fminf(fmaxf(m0, 0.f), 15.f);
    m1 = fminf(fmaxf(m1, 0.f), 15.f);
    m2 = fminf(fmaxf(m2, 0.f), 15.f);
    m3 = fminf(fmaxf(m3, 0.f), 15.f);

    const float4 pv = *reinterpret_cast<const float4*>(pred + (b * HH + y) * WW + x0);
    float e0 = pv.x - m0, e1 = pv.y - m1, e2 = pv.z - m2, e3 = pv.w - m3;
    float e = e0 * e0 + e1 * e1 + e2 * e2 + e3 * e3;

    __shared__ float red[384];
    red[tid] = e;
    __syncthreads();
    if (tid < 128) red[tid] += red[tid + 128] + red[tid + 256];
    __syncthreads();
    if (tid < 64) red[tid] += red[tid + 64];
    __syncthreads();
    if (tid < 32) {
        float v = red[tid] + red[tid + 32];
#pragma unroll
        for (int s = 16; s > 0; s >>= 1) v += __shfl_down_sync(0xffffffffu, v, s);
        if (tid == 0) g_part[blockIdx.y * 96 + blockIdx.x] = v;
    }
}

// ---------------- kernel 5: deterministic final reduce ----------------
__global__ void reduce_kernel(float* __restrict__ out) {
    __shared__ double sh[128];
    const int tid = threadIdx.x;
    double s = 0.0;
    for (int i = tid; i < 384; i += 128) s += (double)g_part[i];
    sh[tid] = s;
    __syncthreads();
    for (int st = 64; st > 0; st >>= 1) {
        if (tid < st) sh[tid] += sh[tid + st];
        __syncthreads();
    }
    if (tid == 0) out[0] = (float)(sh[0] / (double)(BATCH * HH * WW));
}

// ---------------- launcher ----------------
extern "C" void kernel_launch(void* const* d_in, const int* in_sizes, int n_in,
                              void* d_out, int out_size) {
    const float* pred  = (const float*)d_in[0];
    const float* nodes = (const float*)d_in[1];
    float* out = (float*)d_out;
    (void)in_sizes; (void)n_in; (void)out_size;

    conv_kernel<<<dim3(12, 12, BATCH), dim3(32, 8)>>>(pred);
    matgen_kernel<<<NN, NN>>>();
    snake_kernel<<<BATCH, 256>>>(nodes);
    render_kernel<<<dim3(96, BATCH), dim3(96, 4)>>>(pred);
    reduce_kernel<<<1, 128>>>(out);
}

// round 2
// speedup vs baseline: 2.8599x; 2.8599x over previous
#include <cuda_runtime.h>
#include <cuda_bf16.h>
#include <cstdint>

#define BATCH 4
#define HH 384
#define WW 384
#define NN 128
#define RAD 4
#define NSTEPS 50
#define CLIPMAX 382.999f

// ---------------- scratch (static device allocations) ----------------
__device__ float2 g_G [BATCH * HH * WW];   // grad image of pred,  {gy,gx} *10
__device__ float2 g_GW[BATCH * HH * WW];   // grad image of |pred|,{gy,gx} *10
__device__ float  g_M [NN * NN];
__device__ float  g_Mw[NN * NN];
__device__ float2 g_pts[BATCH * NN];
__device__ float  g_wid[BATCH * NN];
__device__ float  g_part[576];

// ---------------- helpers ----------------
typedef unsigned long long ull;

__device__ __forceinline__ float fsqrt_approx(float x) {
    float r; asm("sqrt.approx.f32 %0, %1;" : "=f"(r) : "f"(x)); return r;
}
__device__ __forceinline__ ull pack2(float lo, float hi) {
    ull r; asm("mov.b64 %0, {%1, %2};" : "=l"(r) : "f"(lo), "f"(hi)); return r;
}
__device__ __forceinline__ float2 unpack2(ull v) {
    float2 r; asm("mov.b64 {%0, %1}, %2;" : "=f"(r.x), "=f"(r.y) : "l"(v)); return r;
}
__device__ __forceinline__ void ffma2(ull& d, ull a, ull b) {
    asm("fma.rn.f32x2 %0, %1, %2, %0;" : "+l"(d) : "l"(a), "l"(b));
}

__device__ __forceinline__ float2 bilin(const float2* __restrict__ img, float y, float x) {
    y = fminf(fmaxf(y, 0.f), CLIPMAX);
    x = fminf(fmaxf(x, 0.f), CLIPMAX);
    float fy = floorf(y), fx = floorf(x);
    int   y0 = (int)fy,  x0 = (int)fx;
    float wy = y - fy,   wx = x - fx;
    const float2* p = img + y0 * WW + x0;
    float2 v00 = p[0], v01 = p[1], v10 = p[WW], v11 = p[WW + 1];
    float w00 = (1.f - wy) * (1.f - wx);
    float w01 = (1.f - wy) * wx;
    float w10 = wy * (1.f - wx);
    float w11 = wy * wx;
    float2 r;
    r.x = v00.x * w00 + v01.x * w01 + v10.x * w10 + v11.x * w11;
    r.y = v00.y * w00 + v01.y * w01 + v10.y * w10 + v11.y * w11;
    return r;
}

// ---------------- kernel 1: separable 9x9 gradient conv  +  fused matgen ----------------
// blocks [0,576): conv tiles.  blocks [576,640): M/Mw generation (2 rows each).
__global__ void __launch_bounds__(256) prep_kernel(const float* __restrict__ pred) {
    const int bid = blockIdx.x;
    const int tid = threadIdx.x;

    if (bid < 576) {
        // ---- separable conv: tile 32x32 out, apron 4 ----
        __shared__ float2 tile[40][40];     // {p, |p|}
        __shared__ float4 hs[40][32];       // {Hg_p, Hd_p, Hg_a, Hd_a}

        const int bx = (bid % 12) * 32;
        const int by = ((bid / 12) % 12) * 32;
        const int b  = bid / 144;
        const float* img = pred + b * HH * WW;

        float g[9], dg[9], s = 0.f;
#pragma unroll
        for (int k = 0; k < 9; k++) { float t = (float)(k - 4); g[k] = expf(-t * t * 0.125f); s += g[k]; }
        float inv = 1.f / s;
#pragma unroll
        for (int k = 0; k < 9; k++) { g[k] *= inv; dg[k] = -(float)(k - 4) * 0.25f * g[k]; }

        for (int i = tid; i < 40 * 40; i += 256) {
            int ly = i / 40, lx = i % 40;
            int gy = by - RAD + ly, gx = bx - RAD + lx;
            float v = (gy >= 0 && gy < HH && gx >= 0 && gx < WW) ? img[gy * WW + gx] : 0.f;
            tile[ly][lx] = make_float2(v, fabsf(v));
        }
        __syncthreads();

        // horizontal pass: 40 rows x 32 cols
        for (int i = tid; i < 40 * 32; i += 256) {
            int r = i >> 5, c = i & 31;
            float hgp = 0.f, hdp = 0.f, hga = 0.f, hda = 0.f;
#pragma unroll
            for (int kx = 0; kx < 9; kx++) {
                float2 v = tile[r][c + kx];
                hgp = fmaf(g[kx],  v.x, hgp);
                hdp = fmaf(dg[kx], v.x, hdp);
                hga = fmaf(g[kx],  v.y, hga);
                hda = fmaf(dg[kx], v.y, hda);
            }
            hs[r][c] = make_float4(hgp, hdp, hga, hda);
        }
        __syncthreads();

        // vertical pass: each thread 4 output rows
        const int tx = tid & 31, ty = tid >> 5;
#pragma unroll
        for (int s4 = 0; s4 < 4; s4++) {
            int oy = ty + s4 * 8;
            float c0p = 0.f, c1p = 0.f, c0a = 0.f, c1a = 0.f;
#pragma unroll
            for (int ky = 0; ky < 9; ky++) {
                float4 h = hs[oy + ky][tx];
                c0p = fmaf(dg[ky], h.x, c0p);   // dg_y * Hg  -> channel 0
                c1p = fmaf(g[ky],  h.y, c1p);   // g_y * Hdg  -> channel 1
                c0a = fmaf(dg[ky], h.z, c0a);
                c1a = fmaf(g[ky],  h.w, c1a);
            }
            int o = (b * HH + by + oy) * WW + bx + tx;
            g_G [o] = make_float2(10.f * c0p, 10.f * c1p);
            g_GW[o] = make_float2(10.f * c0a, 10.f * c1a);
        }
    } else {
        // ---- matgen: M, Mw via DCT eigenbasis of path Laplacian ----
        __shared__ float am[2][NN], aw[2][NN];
        const int h = tid >> 7;               // which of the 2 rows in this block
        const int i = (bid - 576) * 2 + h;
        const int j = tid & 127;
        {
            int k = j;
            float lam = 2.f - 2.f * cospif((float)k / 128.f);
            float c2  = (k == 0 ? 1.f : 2.f) / 128.f;
            float dm  = 1.f / (1.f + 0.001f * lam + 0.001f * lam * lam);
            float dw  = 1.f / (1.f + 0.001f * lam);
            float a   = cospif((float)(k * (2 * i + 1)) / 256.f);
            am[h][k] = c2 * dm * a;
            aw[h][k] = c2 * dw * a;
        }
        __syncthreads();
        float sm = 0.f, sw = 0.f;
#pragma unroll 4
        for (int k = 0; k < NN; k++) {
            float bq = cospif((float)(k * (2 * j + 1)) / 256.f);
            sm = fmaf(am[h][k], bq, sm);
            sw = fmaf(aw[h][k], bq, sw);
        }
        g_M [i * NN + j] = sm;
        g_Mw[i * NN + j] = sw;
    }
}

// ---------------- kernel 2: snake evolution ----------------
// 256 threads / sample. thread = (row-pair rp in [0,64), j-quarter q in [0,4)).
// Uses symmetry + centrosymmetry: M[127-i][127-j] = M[i][j].
// Matrices live in registers as {m,m} packed 64-bit pairs; matvecs use fma.rn.f32x2.
__global__ void __launch_bounds__(256) snake_kernel(const float* __restrict__ nodes) {
    const int b   = blockIdx.x;
    const int tid = threadIdx.x;
    const int rp  = tid & 63;       // rows rp and 127-rp
    const int q   = tid >> 6;       // j in [32q, 32q+32)
    const int jb  = q * 32;

    __shared__ __align__(16) float2 ps[NN];        // {y,x}
    __shared__ __align__(16) float2 v2[NN];        // pts + 0.1 f
    __shared__ __align__(16) float2 vwp[64];       // {vw[j], vw[127-j]}
    __shared__ float  wd[NN];
    __shared__ float2 part2[4 * NN];               // pts matvec partials [q][row]
    __shared__ float  partw[4 * NN];               // wid matvec partials [q][row]

    // load matrix coefficients into registers (packed {m,m})
    ull Mp[32], Mwp[32];
    {
        const float4* mr  = reinterpret_cast<const float4*>(g_M  + rp * NN + jb);
        const float4* mwr = reinterpret_cast<const float4*>(g_Mw + rp * NN + jb);
#pragma unroll
        for (int u4 = 0; u4 < 8; u4++) {
            float4 m = __ldg(&mr[u4]);
            Mp[4 * u4 + 0] = pack2(m.x, m.x);
            Mp[4 * u4 + 1] = pack2(m.y, m.y);
            Mp[4 * u4 + 2] = pack2(m.z, m.z);
            Mp[4 * u4 + 3] = pack2(m.w, m.w);
            float4 w = __ldg(&mwr[u4]);
            Mwp[4 * u4 + 0] = pack2(w.x, w.x);
            Mwp[4 * u4 + 1] = pack2(w.y, w.y);
            Mwp[4 * u4 + 2] = pack2(w.z, w.z);
            Mwp[4 * u4 + 3] = pack2(w.w, w.w);
        }
    }

    if (tid < NN) {
        ps[tid] = make_float2(nodes[(b * NN + tid) * 2], nodes[(b * NN + tid) * 2 + 1]);
        wd[tid] = 1.f;
    }
    __syncthreads();

    const float2* Gb  = g_G  + b * HH * WW;
    const float2* GWb = g_GW + b * HH * WW;
    const ull* v2u = reinterpret_cast<const ull*>(v2);
    const ull* vwu = reinterpret_cast<const ull*>(vwp);

    for (int step = 0; step < NSTEPS; step++) {
        // phase 1: combine wid partials (from prev step) + bilinear on G
        if (tid < NN) {
            if (step > 0)
                wd[tid] = partw[tid] + partw[NN + tid] + partw[2 * NN + tid] + partw[3 * NN + tid];
            float2 p = ps[tid];
            float2 f = bilin(Gb, p.x, p.y);
            v2[tid] = make_float2(p.x + 0.1f * f.x, p.y + 0.1f * f.y);
        }
        __syncthreads();

        // phase 2: pts partial matvec (rows rp and 127-rp, j-quarter q)
        {
            ull acc_a = 0ull, acc_b = 0ull;    // row rp, row 127-rp
#pragma unroll
            for (int u = 0; u < 32; u++) {
                int j = jb + u;
                ffma2(acc_a, Mp[u], v2u[j]);
                ffma2(acc_b, Mp[u], v2u[127 - j]);
            }
            part2[q * NN + rp]        = unpack2(acc_a);
            part2[q * NN + 127 - rp]  = unpack2(acc_b);
        }
        __syncthreads();

        // phase 3: combine pts + bilinear on GW -> vw (packed for mirror access)
        if (tid < NN) {
            float2 a = part2[tid], c = part2[NN + tid], d = part2[2 * NN + tid], e = part2[3 * NN + tid];
            float2 p = make_float2(a.x + c.x + d.x + e.x, a.y + c.y + d.y + e.y);
            ps[tid] = p;
            float2 fw = bilin(GWb, p.x, p.y);
            float val = wd[tid] + 0.1f * sqrtf(fw.x * fw.x + fw.y * fw.y);
            if (tid < 64) vwp[tid].x = val;            // vw[j]      (j = tid)
            else          vwp[127 - tid].y = val;      // vw[127-k]  (k = 127-tid)
        }
        __syncthreads();

        // phase 4: wid partial matvec
        {
            ull accw = 0ull;
#pragma unroll
            for (int u = 0; u < 32; u++) {
                int j = jb + u;
                int idx = (q < 2) ? j : (127 - j);
                ffma2(accw, Mwp[u], vwu[idx]);
            }
            float2 aw = unpack2(accw);
            if (q < 2) {
                partw[q * NN + rp]       = aw.x;   // row rp
                partw[q * NN + 127 - rp] = aw.y;   // row 127-rp
            } else {
                partw[q * NN + rp]       = aw.y;
                partw[q * NN + 127 - rp] = aw.x;
            }
        }
        __syncthreads();
    }

    if (tid < NN) {
        float wfin = partw[tid] + partw[NN + tid] + partw[2 * NN + tid] + partw[3 * NN + tid];
        g_pts[b * NN + tid] = ps[tid];
        g_wid[b * NN + tid] = wfin;
    }
}

// ---------------- kernel 3: render with per-tile node shortlist ----------------
// grid (12,12,4): 32x32 tiles. block 256: thread -> (y = t>>3, 4 px at x = (t&7)*4).
__global__ void __launch_bounds__(256) render_kernel(const float* __restrict__ pred) {
    const int b  = blockIdx.z;
    const int x0 = blockIdx.x * 32;
    const int y0 = blockIdx.y * 32;
    const int t  = threadIdx.x;

    __shared__ float4 keep[NN];
    __shared__ float  ur[NN];
    __shared__ int    wcnt[4], wofs[4], cnt;
    __shared__ float  ublim;

    // bounds per node
    float lb = 0.f; float4 nd = make_float4(0, 0, 0, 0); unsigned bmask = 0; bool pred_k = false;
    const float cy = (float)y0 + 15.5f, cx = (float)x0 + 15.5f;
    const float R = 21.95f;
    if (t < NN) {
        float2 p = g_pts[b * NN + t];
        float w  = g_wid[b * NN + t];
        nd = make_float4(p.x, p.y, w, 0.f);
        float dy = p.x - cy, dx = p.y - cx;
        float cd = sqrtf(dy * dy + dx * dx);
        lb = cd - R - w;
        ur[t] = cd + R - w;
    }
    __syncthreads();
    // min-reduce ub
    if (t < 64) ur[t] = fminf(ur[t], ur[t + 64]);
    __syncthreads();
    if (t < 32) {
        float v = fminf(ur[t], ur[t + 32]);
#pragma unroll
        for (int s = 16; s > 0; s >>= 1) v = fminf(v, __shfl_xor_sync(0xffffffffu, v, s));
        if (t == 0) ublim = fminf(v, 15.0f) + 0.02f;
    }
    __syncthreads();

    // deterministic compaction via ballot
    if (t < NN) {
        pred_k = lb < ublim;
        bmask = __ballot_sync(0xffffffffu, pred_k);
        if ((t & 31) == 0) wcnt[t >> 5] = __popc(bmask);
    }
    __syncthreads();
    if (t == 0) {
        int o = 0;
#pragma unroll
        for (int w = 0; w < 4; w++) { wofs[w] = o; o += wcnt[w]; }
        cnt = o;
    }
    __syncthreads();
    if (t < NN && pred_k) {
        int pos = wofs[t >> 5] + __popc(bmask & ((1u << (t & 31)) - 1u));
        keep[pos] = nd;
    }
    __syncthreads();

    const int n = cnt;
    const int y = y0 + (t >> 3);
    const int xg = x0 + (t & 7) * 4;
    const float fy = (float)y, fx0 = (float)xg;
    float m0 = 3.4e38f, m1 = 3.4e38f, m2 = 3.4e38f, m3 = 3.4e38f;

#pragma unroll 4
    for (int k = 0; k < n; k++) {
        float4 kk = keep[k];
        float dy  = fy - kk.x;
        float dy2 = dy * dy;
        float dx0 = fx0 - kk.y;
        float dx1 = dx0 + 1.f, dx2 = dx0 + 2.f, dx3 = dx0 + 3.f;
        m0 = fminf(m0, fsqrt_approx(fmaf(dx0, dx0, dy2)) - kk.z);
        m1 = fminf(m1, fsqrt_approx(fmaf(dx1, dx1, dy2)) - kk.z);
        m2 = fminf(m2, fsqrt_approx(fmaf(dx2, dx2, dy2)) - kk.z);
        m3 = fminf(m3, fsqrt_approx(fmaf(dx3, dx3, dy2)) - kk.z);
    }
    m0 = fminf(fmaxf(m0, 0.f), 15.f);
    m1 = fminf(fmaxf(m1, 0.f), 15.f);
    m2 = fminf(fmaxf(m2, 0.f), 15.f);
    m3 = fminf(fmaxf(m3, 0.f), 15.f);

    const float4 pv = *reinterpret_cast<const float4*>(pred + (b * HH + y) * WW + xg);
    float e0 = pv.x - m0, e1 = pv.y - m1, e2 = pv.z - m2, e3 = pv.w - m3;
    float e = e0 * e0 + e1 * e1 + e2 * e2 + e3 * e3;

    __shared__ float red[256];
    red[t] = e;
    __syncthreads();
    if (t < 128) red[t] += red[t + 128];
    __syncthreads();
    if (t < 64) red[t] += red[t + 64];
    __syncthreads();
    if (t < 32) {
        float v = red[t] + red[t + 32];
#pragma unroll
        for (int s = 16; s > 0; s >>= 1) v += __shfl_down_sync(0xffffffffu, v, s);
        if (t == 0) g_part[(b * 12 + blockIdx.y) * 12 + blockIdx.x] = v;
    }
}

// ---------------- kernel 4: deterministic final reduce ----------------
__global__ void reduce_kernel(float* __restrict__ out) {
    __shared__ double sh[128];
    const int tid = threadIdx.x;
    double s = 0.0;
    for (int i = tid; i < 576; i += 128) s += (double)g_part[i];
    sh[tid] = s;
    __syncthreads();
    for (int st = 64; st > 0; st >>= 1) {
        if (tid < st) sh[tid] += sh[tid + st];
        __syncthreads();
    }
    if (tid == 0) out[0] = (float)(sh[0] / (double)(BATCH * HH * WW));
}

// ---------------- launcher ----------------
extern "C" void kernel_launch(void* const* d_in, const int* in_sizes, int n_in,
                              void* d_out, int out_size) {
    const float* pred  = (const float*)d_in[0];
    const float* nodes = (const float*)d_in[1];
    float* out = (float*)d_out;
    (void)in_sizes; (void)n_in; (void)out_size;

    prep_kernel<<<640, 256>>>(pred);
    snake_kernel<<<BATCH, 256>>>(nodes);
    render_kernel<<<dim3(12, 12, BATCH), 256>>>(pred);
    reduce_kernel<<<1, 128>>>(out);
}

// round 3
// speedup vs baseline: 3.7036x; 1.2950x over previous
#include <cuda_runtime.h>
#include <cuda_bf16.h>
#include <cstdint>

#define BATCH 4
#define HH 384
#define WW 384
#define NN 128
#define RAD 4
#define NSTEPS 50
#define CLIPMAX 382.999f
#define HB 8                    // half-bandwidth of M/Mw band truncation
#define BW (2 * HB + 1)         // 17 taps

// ---------------- scratch (static device allocations) ----------------
__device__ float2 g_G [BATCH * HH * WW];   // grad image of pred,  {gy,gx} *10
__device__ float2 g_GW[BATCH * HH * WW];   // grad image of |pred|,{gy,gx} *10
__device__ float  g_M [NN * NN];
__device__ float  g_Mw[NN * NN];
__device__ float2 g_pts[BATCH * NN];
__device__ float  g_wid[BATCH * NN];
__device__ float  g_part[576];
__device__ unsigned g_cnt;

// ---------------- helpers ----------------
typedef unsigned long long ull;

__device__ __forceinline__ float fsqrt_approx(float x) {
    float r; asm("sqrt.approx.f32 %0, %1;" : "=f"(r) : "f"(x)); return r;
}
__device__ __forceinline__ ull pack2(float lo, float hi) {
    ull r; asm("mov.b64 %0, {%1, %2};" : "=l"(r) : "f"(lo), "f"(hi)); return r;
}
__device__ __forceinline__ float2 unpack2(ull v) {
    float2 r; asm("mov.b64 {%0, %1}, %2;" : "=f"(r.x), "=f"(r.y) : "l"(v)); return r;
}
__device__ __forceinline__ void ffma2(ull& d, ull a, ull b) {
    asm("fma.rn.f32x2 %0, %1, %2, %0;" : "+l"(d) : "l"(a), "l"(b));
}

__device__ __forceinline__ float2 bilin(const float2* __restrict__ img, float y, float x) {
    y = fminf(fmaxf(y, 0.f), CLIPMAX);
    x = fminf(fmaxf(x, 0.f), CLIPMAX);
    float fy = floorf(y), fx = floorf(x);
    int   y0 = (int)fy,  x0 = (int)fx;
    float wy = y - fy,   wx = x - fx;
    const float2* p = img + y0 * WW + x0;
    float2 v00 = __ldg(p), v01 = __ldg(p + 1), v10 = __ldg(p + WW), v11 = __ldg(p + WW + 1);
    float w00 = (1.f - wy) * (1.f - wx);
    float w01 = (1.f - wy) * wx;
    float w10 = wy * (1.f - wx);
    float w11 = wy * wx;
    float2 r;
    r.x = v00.x * w00 + v01.x * w01 + v10.x * w10 + v11.x * w11;
    r.y = v00.y * w00 + v01.y * w01 + v10.y * w10 + v11.y * w11;
    return r;
}

__device__ __forceinline__ void prefetch_bilin(const float2* __restrict__ img, float y, float x) {
    y = fminf(fmaxf(y, 0.f), CLIPMAX);
    x = fminf(fmaxf(x, 0.f), CLIPMAX);
    int y0 = (int)floorf(y), x0 = (int)floorf(x);
    const float2* p = img + y0 * WW + x0;
    asm volatile("prefetch.global.L1 [%0];" :: "l"(p));
    asm volatile("prefetch.global.L1 [%0];" :: "l"(p + 1));
    asm volatile("prefetch.global.L1 [%0];" :: "l"(p + WW));
    asm volatile("prefetch.global.L1 [%0];" :: "l"(p + WW + 1));
}

// ---------------- kernel 1: separable 9x9 gradient conv  +  fused matgen ----------------
// blocks [0,576): conv tiles.  blocks [576,640): M/Mw generation (2 rows each).
__global__ void __launch_bounds__(256) prep_kernel(const float* __restrict__ pred) {
    const int bid = blockIdx.x;
    const int tid = threadIdx.x;

    if (bid < 576) {
        __shared__ float2 tile[40][40];     // {p, |p|}
        __shared__ float4 hs[40][32];       // {Hg_p, Hd_p, Hg_a, Hd_a}

        const int bx = (bid % 12) * 32;
        const int by = ((bid / 12) % 12) * 32;
        const int b  = bid / 144;
        const float* img = pred + b * HH * WW;

        float g[9], dg[9], s = 0.f;
#pragma unroll
        for (int k = 0; k < 9; k++) { float t = (float)(k - 4); g[k] = expf(-t * t * 0.125f); s += g[k]; }
        float inv = 1.f / s;
#pragma unroll
        for (int k = 0; k < 9; k++) { g[k] *= inv; dg[k] = -(float)(k - 4) * 0.25f * g[k]; }

        for (int i = tid; i < 40 * 40; i += 256) {
            int ly = i / 40, lx = i % 40;
            int gy = by - RAD + ly, gx = bx - RAD + lx;
            float v = (gy >= 0 && gy < HH && gx >= 0 && gx < WW) ? img[gy * WW + gx] : 0.f;
            tile[ly][lx] = make_float2(v, fabsf(v));
        }
        __syncthreads();

        for (int i = tid; i < 40 * 32; i += 256) {
            int r = i >> 5, c = i & 31;
            float hgp = 0.f, hdp = 0.f, hga = 0.f, hda = 0.f;
#pragma unroll
            for (int kx = 0; kx < 9; kx++) {
                float2 v = tile[r][c + kx];
                hgp = fmaf(g[kx],  v.x, hgp);
                hdp = fmaf(dg[kx], v.x, hdp);
                hga = fmaf(g[kx],  v.y, hga);
                hda = fmaf(dg[kx], v.y, hda);
            }
            hs[r][c] = make_float4(hgp, hdp, hga, hda);
        }
        __syncthreads();

        const int tx = tid & 31, ty = tid >> 5;
#pragma unroll
        for (int s4 = 0; s4 < 4; s4++) {
            int oy = ty + s4 * 8;
            float c0p = 0.f, c1p = 0.f, c0a = 0.f, c1a = 0.f;
#pragma unroll
            for (int ky = 0; ky < 9; ky++) {
                float4 h = hs[oy + ky][tx];
                c0p = fmaf(dg[ky], h.x, c0p);
                c1p = fmaf(g[ky],  h.y, c1p);
                c0a = fmaf(dg[ky], h.z, c0a);
                c1a = fmaf(g[ky],  h.w, c1a);
            }
            int o = (b * HH + by + oy) * WW + bx + tx;
            g_G [o] = make_float2(10.f * c0p, 10.f * c1p);
            g_GW[o] = make_float2(10.f * c0a, 10.f * c1a);
        }
    } else {
        // ---- matgen: M, Mw via DCT eigenbasis of path Laplacian ----
        __shared__ float am[2][NN], aw[2][NN];
        const int h = tid >> 7;
        const int i = (bid - 576) * 2 + h;
        const int j = tid & 127;
        if (bid == 576 && tid == 0) g_cnt = 0;     // reset render completion counter
        {
            int k = j;
            float lam = 2.f - 2.f * cospif((float)k / 128.f);
            float c2  = (k == 0 ? 1.f : 2.f) / 128.f;
            float dm  = 1.f / (1.f + 0.001f * lam + 0.001f * lam * lam);
            float dw  = 1.f / (1.f + 0.001f * lam);
            float a   = cospif((float)(k * (2 * i + 1)) / 256.f);
            am[h][k] = c2 * dm * a;
            aw[h][k] = c2 * dw * a;
        }
        __syncthreads();
        float sm = 0.f, sw = 0.f;
#pragma unroll 4
        for (int k = 0; k < NN; k++) {
            float bq = cospif((float)(k * (2 * j + 1)) / 256.f);
            sm = fmaf(am[h][k], bq, sm);
            sw = fmaf(aw[h][k], bq, sw);
        }
        g_M [i * NN + j] = sm;
        g_Mw[i * NN + j] = sw;
    }
}

// ---------------- kernel 2: snake evolution (banded matvec + L1 prefetch) ----------------
// 128 threads / sample, thread i owns node i. M/Mw truncated to half-bandwidth 8
// (truncation error ~3e-9: Neumann tail of (0.001L+0.001L^2)).
__global__ void __launch_bounds__(128) snake_kernel(const float* __restrict__ nodes) {
    const int b = blockIdx.x;
    const int i = threadIdx.x;

    __shared__ __align__(16) float2 v2pad[NN + 2 * HB];
    __shared__ __align__(16) float  vwpad[NN + 2 * HB];
    const ull* v2u = reinterpret_cast<const ull*>(v2pad);

    // zero the pads once
    if (i < HB) {
        v2pad[i] = make_float2(0.f, 0.f);
        v2pad[NN + HB + i] = make_float2(0.f, 0.f);
        vwpad[i] = 0.f;
        vwpad[NN + HB + i] = 0.f;
    }

    // load band rows into registers (clipped at matrix edges -> 0 coeff)
    ull   Mp[BW];
    float Mw[BW];
#pragma unroll
    for (int u = 0; u < BW; u++) {
        int j = i - HB + u;
        bool ok = (j >= 0) && (j < NN);
        float m  = ok ? __ldg(&g_M [i * NN + j]) : 0.f;
        float mw = ok ? __ldg(&g_Mw[i * NN + j]) : 0.f;
        Mp[u] = pack2(m, m);
        Mw[u] = mw;
    }

    float2 p = make_float2(__ldg(&nodes[(b * NN + i) * 2]), __ldg(&nodes[(b * NN + i) * 2 + 1]));
    float  wd = 1.f;

    const float2* Gb  = g_G  + b * HH * WW;
    const float2* GWb = g_GW + b * HH * WW;
    __syncthreads();

    for (int step = 0; step < NSTEPS; step++) {
        // A: external force at current pts; prefetch GW lines (new pts ~= old pts)
        float2 f = bilin(Gb, p.x, p.y);
        prefetch_bilin(GWb, p.x, p.y);
        v2pad[HB + i] = make_float2(p.x + 0.1f * f.x, p.y + 0.1f * f.y);
        __syncthreads();

        // B: pts = M @ v2 (banded), then width force at new pts; prefetch G for next step
        {
            ull a0 = 0ull, a1 = 0ull;
#pragma unroll
            for (int u = 0; u < BW - 1; u += 2) {
                ffma2(a0, Mp[u],     v2u[i + u]);
                ffma2(a1, Mp[u + 1], v2u[i + u + 1]);
            }
            ffma2(a0, Mp[BW - 1], v2u[i + BW - 1]);
            float2 ra = unpack2(a0), rb = unpack2(a1);
            p = make_float2(ra.x + rb.x, ra.y + rb.y);
        }
        float2 fw = bilin(GWb, p.x, p.y);
        prefetch_bilin(Gb, p.x, p.y);
        vwpad[HB + i] = wd + 0.1f * sqrtf(fw.x * fw.x + fw.y * fw.y);
        __syncthreads();

        // C: wid = Mw @ vw (banded); no barrier needed (next write hits v2pad after bar A')
        {
            float a0 = 0.f, a1 = 0.f;
#pragma unroll
            for (int u = 0; u < BW - 1; u += 2) {
                a0 = fmaf(Mw[u],     vwpad[i + u],     a0);
                a1 = fmaf(Mw[u + 1], vwpad[i + u + 1], a1);
            }
            a0 = fmaf(Mw[BW - 1], vwpad[i + BW - 1], a0);
            wd = a0 + a1;
        }
    }

    g_pts[b * NN + i] = p;
    g_wid[b * NN + i] = wd;
}

// ---------------- kernel 3: render + shortlist + fused final reduce ----------------
__global__ void __launch_bounds__(256) render_kernel(const float* __restrict__ pred,
                                                     float* __restrict__ out) {
    const int b  = blockIdx.z;
    const int x0 = blockIdx.x * 32;
    const int y0 = blockIdx.y * 32;
    const int t  = threadIdx.x;

    __shared__ float4 keep[NN];
    __shared__ float  ur[NN];
    __shared__ int    wcnt[4], wofs[4], cnt;
    __shared__ float  ublim;

    float lb = 0.f; float4 nd = make_float4(0, 0, 0, 0); unsigned bmask = 0; bool pred_k = false;
    const float cy = (float)y0 + 15.5f, cx = (float)x0 + 15.5f;
    const float R = 21.95f;
    if (t < NN) {
        float2 p = g_pts[b * NN + t];
        float w  = g_wid[b * NN + t];
        nd = make_float4(p.x, p.y, w, 0.f);
        float dy = p.x - cy, dx = p.y - cx;
        float cd = sqrtf(dy * dy + dx * dx);
        lb = cd - R - w;
        ur[t] = cd + R - w;
    }
    __syncthreads();
    if (t < 64) ur[t] = fminf(ur[t], ur[t + 64]);
    __syncthreads();
    if (t < 32) {
        float v = fminf(ur[t], ur[t + 32]);
#pragma unroll
        for (int s = 16; s > 0; s >>= 1) v = fminf(v, __shfl_xor_sync(0xffffffffu, v, s));
        if (t == 0) ublim = fminf(v, 15.0f) + 0.02f;
    }
    __syncthreads();

    if (t < NN) {
        pred_k = lb < ublim;
        bmask = __ballot_sync(0xffffffffu, pred_k);
        if ((t & 31) == 0) wcnt[t >> 5] = __popc(bmask);
    }
    __syncthreads();
    if (t == 0) {
        int o = 0;
#pragma unroll
        for (int w = 0; w < 4; w++) { wofs[w] = o; o += wcnt[w]; }
        cnt = o;
    }
    __syncthreads();
    if (t < NN && pred_k) {
        int pos = wofs[t >> 5] + __popc(bmask & ((1u << (t & 31)) - 1u));
        keep[pos] = nd;
    }
    __syncthreads();

    const int n = cnt;
    const int y = y0 + (t >> 3);
    const int xg = x0 + (t & 7) * 4;
    const float fy = (float)y, fx0 = (float)xg;
    float m0 = 3.4e38f, m1 = 3.4e38f, m2 = 3.4e38f, m3 = 3.4e38f;

#pragma unroll 4
    for (int k = 0; k < n; k++) {
        float4 kk = keep[k];
        float dy  = fy - kk.x;
        float dy2 = dy * dy;
        float dx0 = fx0 - kk.y;
        float dx1 = dx0 + 1.f, dx2 = dx0 + 2.f, dx3 = dx0 + 3.f;
        m0 = fminf(m0, fsqrt_approx(fmaf(dx0, dx0, dy2)) - kk.z);
        m1 = fminf(m1, fsqrt_approx(fmaf(dx1, dx1, dy2)) - kk.z);
        m2 = fminf(m2, fsqrt_approx(fmaf(dx2, dx2, dy2)) - kk.z);
        m3 = fminf(m3, fsqrt_approx(fmaf(dx3, dx3, dy2)) - kk.z);
    }
    m0 = fminf(fmaxf(m0, 0.f), 15.f);
    m1 = fminf(fmaxf(m1, 0.f), 15.f);
    m2 = fminf(fmaxf(m2, 0.f), 15.f);
    m3 = fminf(fmaxf(m3, 0.f), 15.f);

    const float4 pv = *reinterpret_cast<const float4*>(pred + (b * HH + y) * WW + xg);
    float e0 = pv.x - m0, e1 = pv.y - m1, e2 = pv.z - m2, e3 = pv.w - m3;
    float e = e0 * e0 + e1 * e1 + e2 * e2 + e3 * e3;

    __shared__ float red[256];
    red[t] = e;
    __syncthreads();
    if (t < 128) red[t] += red[t + 128];
    __syncthreads();
    if (t < 64) red[t] += red[t + 64];
    __syncthreads();
    if (t < 32) {
        float v = red[t] + red[t + 32];
#pragma unroll
        for (int s = 16; s > 0; s >>= 1) v += __shfl_down_sync(0xffffffffu, v, s);
        if (t == 0) g_part[(b * 12 + blockIdx.y) * 12 + blockIdx.x] = v;
    }

    // fused deterministic final reduce: last block to finish sums fixed array in fixed order
    __shared__ bool amLast;
    if (t == 0) {
        __threadfence();
        unsigned v = atomicAdd(&g_cnt, 1u);
        amLast = (v == 575u);
    }
    __syncthreads();
    if (amLast) {
        __shared__ double sh[256];
        double s = 0.0;
        for (int idx = t; idx < 576; idx += 256) s += (double)g_part[idx];
        sh[t] = s;
        __syncthreads();
        for (int st = 128; st > 0; st >>= 1) {
            if (t < st) sh[t] += sh[t + st];
            __syncthreads();
        }
        if (t == 0) out[0] = (float)(sh[0] / (double)(BATCH * HH * WW));
    }
}

// ---------------- launcher ----------------
extern "C" void kernel_launch(void* const* d_in, const int* in_sizes, int n_in,
                              void* d_out, int out_size) {
    const float* pred  = (const float*)d_in[0];
    const float* nodes = (const float*)d_in[1];
    float* out = (float*)d_out;
    (void)in_sizes; (void)n_in; (void)out_size;

    prep_kernel<<<640, 256>>>(pred);
    snake_kernel<<<BATCH, 128>>>(nodes);
    render_kernel<<<dim3(12, 12, BATCH), 256>>>(pred, out);
}